// round 1
// baseline (speedup 1.0000x reference)
#include <cuda_runtime.h>

#define HDIM 2048
#define MDIM 1408
#define NEXP 8
#define NTOK 1024

// ---------------- device scratch (no runtime allocation allowed) ----------------
__device__ float g_Abuf[NEXP * NTOK * MDIM];   // routed SwiGLU activations, slot = e*NTOK + pos
__device__ float g_Smid[NTOK * MDIM];          // shared-expert SwiGLU activations
__device__ int   g_tok[NEXP * NTOK];           // gathered token index per expert slot
__device__ float g_wt[NEXP * NTOK];            // normalized routing weight per expert slot
__device__ int   g_cnt[NEXP];                  // tokens routed to each expert
__device__ float g_pisum[NEXP];                // sum of softmax scores per expert (for aux)

// ---------------- init ----------------
__global__ void zero_kernel(float* __restrict__ y) {
    int i = blockIdx.x * blockDim.x + threadIdx.x;
    if (i < NTOK * HDIM) y[i] = 0.f;
    if (i < NEXP) { g_cnt[i] = 0; g_pisum[i] = 0.f; }
}

// ---------------- gate: logits -> softmax -> top2 -> scatter ----------------
__global__ __launch_bounds__(256)
void gate_kernel(const float* __restrict__ x, const float* __restrict__ gw) {
    const int t = blockIdx.x;
    const float* xr = x + (size_t)t * HDIM;

    float acc[NEXP];
#pragma unroll
    for (int e = 0; e < NEXP; e++) acc[e] = 0.f;

    for (int h = threadIdx.x; h < HDIM; h += 256) {
        float xv = xr[h];
#pragma unroll
        for (int e = 0; e < NEXP; e++) acc[e] = fmaf(xv, gw[e * HDIM + h], acc[e]);
    }
#pragma unroll
    for (int e = 0; e < NEXP; e++)
        for (int o = 16; o > 0; o >>= 1) acc[e] += __shfl_down_sync(0xffffffffu, acc[e], o);

    __shared__ float red[8][NEXP];
    int warp = threadIdx.x >> 5, lane = threadIdx.x & 31;
    if (lane == 0) {
#pragma unroll
        for (int e = 0; e < NEXP; e++) red[warp][e] = acc[e];
    }
    __syncthreads();

    if (threadIdx.x == 0) {
        float lg[NEXP];
#pragma unroll
        for (int e = 0; e < NEXP; e++) {
            float s = 0.f;
            for (int w = 0; w < 8; w++) s += red[w][e];
            lg[e] = s;
        }
        // softmax over 8 experts
        float mx = lg[0];
#pragma unroll
        for (int e = 1; e < NEXP; e++) mx = fmaxf(mx, lg[e]);
        float p[NEXP]; float den = 0.f;
#pragma unroll
        for (int e = 0; e < NEXP; e++) { p[e] = __expf(lg[e] - mx); den += p[e]; }
#pragma unroll
        for (int e = 0; e < NEXP; e++) p[e] /= den;

        // pi accumulation for aux loss
#pragma unroll
        for (int e = 0; e < NEXP; e++) atomicAdd(&g_pisum[e], p[e]);

        // top-2 (strict > keeps lowest index on tie, matching jax top_k)
        int i1 = 0;
#pragma unroll
        for (int e = 1; e < NEXP; e++) if (p[e] > p[i1]) i1 = e;
        int i2 = -1;
#pragma unroll
        for (int e = 0; e < NEXP; e++) {
            if (e == i1) continue;
            if (i2 < 0 || p[e] > p[i2]) i2 = e;
        }
        float w1 = p[i1], w2 = p[i2];
        float s2 = w1 + w2 + 1e-20f;
        w1 /= s2; w2 /= s2;

        int pos1 = atomicAdd(&g_cnt[i1], 1);
        g_tok[i1 * NTOK + pos1] = t; g_wt[i1 * NTOK + pos1] = w1;
        int pos2 = atomicAdd(&g_cnt[i2], 1);
        g_tok[i2 * NTOK + pos2] = t; g_wt[i2 * NTOK + pos2] = w2;
    }
}

// ---------------- gathered gate/up GEMM with fused SiLU*up ----------------
// C[r, m] = silu(X_e @ Wg^T) * (X_e @ Wu^T), tiles 64x64x16, 256 thr, 4x4 dual-acc
template<bool SHARED>
__global__ __launch_bounds__(256)
void gateup_kernel(const float* __restrict__ x,
                   const float* __restrict__ wgate,
                   const float* __restrict__ wup) {
    const int e = SHARED ? 0 : blockIdx.z;
    const int nrows = SHARED ? NTOK : g_cnt[e];
    const int row0 = blockIdx.x * 64;
    if (row0 >= nrows) return;
    const int n0 = blockIdx.y * 64;
    const float* wg = wgate + (SHARED ? 0 : (size_t)e * MDIM * HDIM);
    const float* wu = wup   + (SHARED ? 0 : (size_t)e * MDIM * HDIM);

    __shared__ float As[16][64];
    __shared__ float Bg[16][64];
    __shared__ float Bu[16][64];
    __shared__ int   toks[64];

    const int tid = threadIdx.x;
    if (tid < 64) {
        int r = row0 + tid;
        int tk = -1;
        if (r < nrows) tk = SHARED ? r : g_tok[e * NTOK + r];
        toks[tid] = tk;
    }
    __syncthreads();

    const int lr = tid >> 2;
    const int lk = (tid & 3) << 2;
    const int tx = tid & 15;
    const int ty = tid >> 4;

    const int tk_my = toks[lr];
    const float* arow = (tk_my >= 0) ? x + (size_t)tk_my * HDIM : nullptr;
    const float* grow = wg + (size_t)(n0 + lr) * HDIM;
    const float* urow = wu + (size_t)(n0 + lr) * HDIM;

    float accg[4][4] = {}, accu[4][4] = {};

    for (int k0 = 0; k0 < HDIM; k0 += 16) {
        float4 av = arow ? *(const float4*)(arow + k0 + lk) : make_float4(0.f, 0.f, 0.f, 0.f);
        float4 gv = *(const float4*)(grow + k0 + lk);
        float4 uv = *(const float4*)(urow + k0 + lk);
        As[lk + 0][lr] = av.x; As[lk + 1][lr] = av.y; As[lk + 2][lr] = av.z; As[lk + 3][lr] = av.w;
        Bg[lk + 0][lr] = gv.x; Bg[lk + 1][lr] = gv.y; Bg[lk + 2][lr] = gv.z; Bg[lk + 3][lr] = gv.w;
        Bu[lk + 0][lr] = uv.x; Bu[lk + 1][lr] = uv.y; Bu[lk + 2][lr] = uv.z; Bu[lk + 3][lr] = uv.w;
        __syncthreads();
#pragma unroll
        for (int kk = 0; kk < 16; kk++) {
            float4 a  = *(const float4*)&As[kk][ty << 2];
            float4 bg = *(const float4*)&Bg[kk][tx << 2];
            float4 bu = *(const float4*)&Bu[kk][tx << 2];
            float ar[4]  = { a.x,  a.y,  a.z,  a.w };
            float bgr[4] = { bg.x, bg.y, bg.z, bg.w };
            float bur[4] = { bu.x, bu.y, bu.z, bu.w };
#pragma unroll
            for (int i = 0; i < 4; i++)
#pragma unroll
                for (int j = 0; j < 4; j++) {
                    accg[i][j] = fmaf(ar[i], bgr[j], accg[i][j]);
                    accu[i][j] = fmaf(ar[i], bur[j], accu[i][j]);
                }
        }
        __syncthreads();
    }

#pragma unroll
    for (int i = 0; i < 4; i++) {
        int r = row0 + (ty << 2) + i;
        if (r >= nrows) continue;
        size_t slot = SHARED ? (size_t)r : (size_t)e * NTOK + r;
        float* orow = (SHARED ? g_Smid : g_Abuf) + slot * MDIM + n0 + (tx << 2);
#pragma unroll
        for (int j = 0; j < 4; j++) {
            float g = accg[i][j];
            float s = g / (1.f + __expf(-g));
            orow[j] = s * accu[i][j];
        }
    }
}

// ---------------- down GEMM + weighted scatter into y ----------------
template<bool SHARED>
__global__ __launch_bounds__(256)
void down_kernel(const float* __restrict__ wdown, float* __restrict__ y) {
    const int e = SHARED ? 0 : blockIdx.z;
    const int nrows = SHARED ? NTOK : g_cnt[e];
    const int row0 = blockIdx.x * 64;
    if (row0 >= nrows) return;
    const int h0 = blockIdx.y * 64;
    const float* wd = wdown + (SHARED ? 0 : (size_t)e * HDIM * MDIM);
    const float* Ab = SHARED ? g_Smid : (g_Abuf + (size_t)e * NTOK * MDIM);

    __shared__ float As[16][64];
    __shared__ float Bs[16][64];
    __shared__ int   toks[64];
    __shared__ float wts[64];

    const int tid = threadIdx.x;
    if (tid < 64) {
        int r = row0 + tid;
        if (r < nrows) {
            toks[tid] = SHARED ? r : g_tok[e * NTOK + r];
            wts[tid]  = SHARED ? 1.f : g_wt[e * NTOK + r];
        } else { toks[tid] = 0; wts[tid] = 0.f; }
    }
    __syncthreads();

    const int lr = tid >> 2;
    const int lk = (tid & 3) << 2;
    const int tx = tid & 15;
    const int ty = tid >> 4;

    const int rA = row0 + lr;
    const float* arow = (rA < nrows) ? Ab + (size_t)rA * MDIM : nullptr;
    const float* brow = wd + (size_t)(h0 + lr) * MDIM;

    float acc[4][4] = {};

    for (int k0 = 0; k0 < MDIM; k0 += 16) {
        float4 av = arow ? *(const float4*)(arow + k0 + lk) : make_float4(0.f, 0.f, 0.f, 0.f);
        float4 bv = *(const float4*)(brow + k0 + lk);
        As[lk + 0][lr] = av.x; As[lk + 1][lr] = av.y; As[lk + 2][lr] = av.z; As[lk + 3][lr] = av.w;
        Bs[lk + 0][lr] = bv.x; Bs[lk + 1][lr] = bv.y; Bs[lk + 2][lr] = bv.z; Bs[lk + 3][lr] = bv.w;
        __syncthreads();
#pragma unroll
        for (int kk = 0; kk < 16; kk++) {
            float4 a = *(const float4*)&As[kk][ty << 2];
            float4 b = *(const float4*)&Bs[kk][tx << 2];
            float ar[4] = { a.x, a.y, a.z, a.w };
            float br[4] = { b.x, b.y, b.z, b.w };
#pragma unroll
            for (int i = 0; i < 4; i++)
#pragma unroll
                for (int j = 0; j < 4; j++)
                    acc[i][j] = fmaf(ar[i], br[j], acc[i][j]);
        }
        __syncthreads();
    }

#pragma unroll
    for (int i = 0; i < 4; i++) {
        int r = row0 + (ty << 2) + i;
        if (r >= nrows) continue;
        float w = wts[(ty << 2) + i];
        float* yrow = y + (size_t)toks[(ty << 2) + i] * HDIM + h0 + (tx << 2);
#pragma unroll
        for (int j = 0; j < 4; j++)
            atomicAdd(&yrow[j], acc[i][j] * w);
    }
}

// ---------------- aux loss (b=1, seq_aux closed form) ----------------
__global__ void aux_kernel(float* __restrict__ p) {
    float a = 0.f;
#pragma unroll
    for (int e = 0; e < NEXP; e++) {
        float ce = (float)g_cnt[e] * ((float)NEXP / (float)(NTOK * 2));  // cnt / (S*K/E)
        float pi = g_pisum[e] / (float)NTOK;
        a += ce * pi;
    }
    *p = a * 0.001f;
}

// ---------------- launch ----------------
extern "C" void kernel_launch(void* const* d_in, const int* in_sizes, int n_in,
                              void* d_out, int out_size) {
    (void)in_sizes; (void)n_in;
    const float* x   = (const float*)d_in[0];  // [1,1024,2048]
    const float* gw  = (const float*)d_in[1];  // [8,2048]
    const float* wgt = (const float*)d_in[2];  // [8,1408,2048]
    const float* wup = (const float*)d_in[3];  // [8,1408,2048]
    const float* wdn = (const float*)d_in[4];  // [8,2048,1408]
    const float* shg = (const float*)d_in[5];  // [1408,2048]
    const float* shu = (const float*)d_in[6];  // [1408,2048]
    const float* shd = (const float*)d_in[7];  // [2048,1408]
    float* y = (float*)d_out;

    zero_kernel<<<(NTOK * HDIM + 255) / 256, 256>>>(y);
    gate_kernel<<<NTOK, 256>>>(x, gw);

    gateup_kernel<false><<<dim3(NTOK / 64, MDIM / 64, NEXP), 256>>>(x, wgt, wup);
    gateup_kernel<true ><<<dim3(NTOK / 64, MDIM / 64, 1),    256>>>(x, shg, shu);

    down_kernel<false><<<dim3(NTOK / 64, HDIM / 64, NEXP), 256>>>(wdn, y);
    down_kernel<true ><<<dim3(NTOK / 64, HDIM / 64, 1),    256>>>(shd, y);

    if (out_size > NTOK * HDIM)
        aux_kernel<<<1, 1>>>(y + NTOK * HDIM);
}

// round 3
// speedup vs baseline: 1.5028x; 1.5028x over previous
#include <cuda_runtime.h>
#include <cuda_bf16.h>
#include <cstdint>

#define HDIM 2048
#define MDIM 1408
#define NEXP 8
#define NTOK 1024

// ---------------- device scratch ----------------
__device__ __nv_bfloat16 g_xhi[NTOK * HDIM];
__device__ __nv_bfloat16 g_xlo[NTOK * HDIM];
__device__ __nv_bfloat16 g_ahi[(NEXP + 1) * NTOK * MDIM];
__device__ __nv_bfloat16 g_alo[(NEXP + 1) * NTOK * MDIM];
__device__ int   g_tok[NEXP * NTOK];
__device__ float g_wt[NEXP * NTOK];
__device__ int   g_cnt[NEXP];
__device__ float g_pisum[NEXP];

// ---------------- helpers ----------------
__device__ __forceinline__ uint32_t smem_u32(const void* p) {
    uint32_t a;
    asm("{ .reg .u64 t; cvta.to.shared.u64 t, %1; cvt.u32.u64 %0, t; }" : "=r"(a) : "l"(p));
    return a;
}

#define LDSM4(r, addr)                                                                       \
    asm volatile("ldmatrix.sync.aligned.m8n8.x4.shared.b16 {%0,%1,%2,%3}, [%4];"             \
                 : "=r"((r)[0]), "=r"((r)[1]), "=r"((r)[2]), "=r"((r)[3]) : "r"(addr))
#define LDSM2(r, addr)                                                                       \
    asm volatile("ldmatrix.sync.aligned.m8n8.x2.shared.b16 {%0,%1}, [%2];"                   \
                 : "=r"((r)[0]), "=r"((r)[1]) : "r"(addr))
#define MMA(c, a, b)                                                                         \
    asm volatile("mma.sync.aligned.m16n8k16.row.col.f32.bf16.bf16.f32 "                      \
                 "{%0,%1,%2,%3},{%4,%5,%6,%7},{%8,%9},{%0,%1,%2,%3};"                        \
                 : "+f"((c)[0]), "+f"((c)[1]), "+f"((c)[2]), "+f"((c)[3])                    \
                 : "r"((a)[0]), "r"((a)[1]), "r"((a)[2]), "r"((a)[3]), "r"((b)[0]), "r"((b)[1]))

__device__ __forceinline__ void split2(float a, float b, uint32_t& hi, uint32_t& lo) {
    __nv_bfloat16 ha = __float2bfloat16(a), hb = __float2bfloat16(b);
    float ra = a - __bfloat162float(ha), rb = b - __bfloat162float(hb);
    __nv_bfloat16 la = __float2bfloat16(ra), lb = __float2bfloat16(rb);
    __nv_bfloat162 hp; hp.x = ha; hp.y = hb;
    __nv_bfloat162 lp; lp.x = la; lp.y = lb;
    hi = *reinterpret_cast<uint32_t*>(&hp);
    lo = *reinterpret_cast<uint32_t*>(&lp);
}
__device__ __forceinline__ void split8(const float4& a, const float4& b, uint4& hi, uint4& lo) {
    split2(a.x, a.y, hi.x, lo.x);
    split2(a.z, a.w, hi.y, lo.y);
    split2(b.x, b.y, hi.z, lo.z);
    split2(b.z, b.w, hi.w, lo.w);
}

#define LDS_ROW 80   // bytes per SMEM row (32 bf16 + 16B pad) -> conflict-free ldmatrix

// ---------------- init ----------------
__global__ void zero_kernel(float* __restrict__ y) {
    int i = blockIdx.x * blockDim.x + threadIdx.x;
    if (i < NTOK * HDIM) y[i] = 0.f;
    if (i < NEXP) { g_cnt[i] = 0; g_pisum[i] = 0.f; }
}

__global__ void xconv_kernel(const float* __restrict__ x) {
    int i = blockIdx.x * blockDim.x + threadIdx.x;
    if (i < NTOK * HDIM) {
        float v = x[i];
        __nv_bfloat16 h = __float2bfloat16(v);
        __nv_bfloat16 l = __float2bfloat16(v - __bfloat162float(h));
        g_xhi[i] = h; g_xlo[i] = l;
    }
}

// ---------------- gate ----------------
__global__ __launch_bounds__(256)
void gate_kernel(const float* __restrict__ x, const float* __restrict__ gw) {
    const int t = blockIdx.x;
    const float* xr = x + (size_t)t * HDIM;
    float acc[NEXP];
#pragma unroll
    for (int e = 0; e < NEXP; e++) acc[e] = 0.f;
    for (int h = threadIdx.x; h < HDIM; h += 256) {
        float xv = xr[h];
#pragma unroll
        for (int e = 0; e < NEXP; e++) acc[e] = fmaf(xv, gw[e * HDIM + h], acc[e]);
    }
#pragma unroll
    for (int e = 0; e < NEXP; e++)
        for (int o = 16; o > 0; o >>= 1) acc[e] += __shfl_down_sync(0xffffffffu, acc[e], o);

    __shared__ float red[8][NEXP];
    int warp = threadIdx.x >> 5, lane = threadIdx.x & 31;
    if (lane == 0) {
#pragma unroll
        for (int e = 0; e < NEXP; e++) red[warp][e] = acc[e];
    }
    __syncthreads();
    if (threadIdx.x == 0) {
        float lg[NEXP];
#pragma unroll
        for (int e = 0; e < NEXP; e++) {
            float s = 0.f;
            for (int w = 0; w < 8; w++) s += red[w][e];
            lg[e] = s;
        }
        float mx = lg[0];
#pragma unroll
        for (int e = 1; e < NEXP; e++) mx = fmaxf(mx, lg[e]);
        float p[NEXP]; float den = 0.f;
#pragma unroll
        for (int e = 0; e < NEXP; e++) { p[e] = __expf(lg[e] - mx); den += p[e]; }
#pragma unroll
        for (int e = 0; e < NEXP; e++) p[e] /= den;
#pragma unroll
        for (int e = 0; e < NEXP; e++) atomicAdd(&g_pisum[e], p[e]);
        int i1 = 0;
#pragma unroll
        for (int e = 1; e < NEXP; e++) if (p[e] > p[i1]) i1 = e;
        int i2 = -1;
#pragma unroll
        for (int e = 0; e < NEXP; e++) {
            if (e == i1) continue;
            if (i2 < 0 || p[e] > p[i2]) i2 = e;
        }
        float w1 = p[i1], w2 = p[i2];
        float s2 = w1 + w2 + 1e-20f;
        w1 /= s2; w2 /= s2;
        int pos1 = atomicAdd(&g_cnt[i1], 1);
        g_tok[i1 * NTOK + pos1] = t; g_wt[i1 * NTOK + pos1] = w1;
        int pos2 = atomicAdd(&g_cnt[i2], 1);
        g_tok[i2 * NTOK + pos2] = t; g_wt[i2 * NTOK + pos2] = w2;
    }
}

// =======================================================================
// gateup: act[slot, m] = silu(X Wg^T) * (X Wu^T)   (tile 128x64, K chunk 32)
// =======================================================================
#define GU_AHI 0
#define GU_ALO 10240
#define GU_BGH 20480
#define GU_BGL 25600
#define GU_BUH 30720
#define GU_BUL 35840
#define GU_TOK 40960
#define GU_SM  41472

template<bool SHARED>
__global__ __launch_bounds__(256)
void gateup_mma(const float* __restrict__ wgate, const float* __restrict__ wup) {
    __shared__ __align__(16) char sm[GU_SM];
    const int e = SHARED ? 0 : blockIdx.z;
    const int eSlot = SHARED ? NEXP : blockIdx.z;
    const int nrows = SHARED ? NTOK : g_cnt[e];
    const int row0 = blockIdx.x * 128;
    if (row0 >= nrows) return;
    const int n0 = blockIdx.y * 64;
    const float* wg = wgate + (SHARED ? 0 : (size_t)e * MDIM * HDIM);
    const float* wu = wup   + (SHARED ? 0 : (size_t)e * MDIM * HDIM);

    const int tid = threadIdx.x, wid = tid >> 5, lane = tid & 31;
    int* toks = (int*)(sm + GU_TOK);
    if (tid < 128) {
        int r = row0 + tid;
        toks[tid] = (r < nrows) ? (SHARED ? r : g_tok[e * NTOK + r]) : 0;
    }
    __syncthreads();

    // global load mapping
    const int arow = tid >> 1, aseg = tid & 1;
    const __nv_bfloat16* aph = g_xhi + (size_t)toks[arow] * HDIM + aseg * 16;
    const __nv_bfloat16* apl = g_xlo + (size_t)toks[arow] * HDIM + aseg * 16;
    const int brow = tid >> 2, bseg = tid & 3;
    const float* gp = wg + (size_t)(n0 + brow) * HDIM + bseg * 8;
    const float* up = wu + (size_t)(n0 + brow) * HDIM + bseg * 8;

    uint4 rah[2], ral[2];
    float4 rbg[2], rbu[2];
#define GU_LOAD(k0) do {                                                   \
    rah[0] = *(const uint4*)(aph + (k0));  rah[1] = *(const uint4*)(aph + (k0) + 8); \
    ral[0] = *(const uint4*)(apl + (k0));  ral[1] = *(const uint4*)(apl + (k0) + 8); \
    rbg[0] = *(const float4*)(gp + (k0));  rbg[1] = *(const float4*)(gp + (k0) + 4); \
    rbu[0] = *(const float4*)(up + (k0));  rbu[1] = *(const float4*)(up + (k0) + 4); \
} while (0)

    const uint32_t sb = smem_u32(sm);
    const int wm = wid & 1, wn = wid >> 1;            // 2 x 4 warp grid, warp tile 64x16
    const uint32_t aOffL = (lane & 15) * LDS_ROW + (lane >> 4) * 16;
    const uint32_t bOffL = (lane & 7) * LDS_ROW + ((lane >> 3) & 1) * 16;
    const uint32_t aHiB = sb + GU_AHI + (wm * 64) * LDS_ROW + aOffL;
    const uint32_t aLoB = sb + GU_ALO + (wm * 64) * LDS_ROW + aOffL;
    const uint32_t bGH = sb + GU_BGH + (wn * 16) * LDS_ROW + bOffL;
    const uint32_t bGL = sb + GU_BGL + (wn * 16) * LDS_ROW + bOffL;
    const uint32_t bUH = sb + GU_BUH + (wn * 16) * LDS_ROW + bOffL;
    const uint32_t bUL = sb + GU_BUL + (wn * 16) * LDS_ROW + bOffL;

    const uint32_t aSt = arow * LDS_ROW + aseg * 32;
    const uint32_t bSt = brow * LDS_ROW + bseg * 16;

    float accg[4][2][4] = {}, accu[4][2][4] = {};

    GU_LOAD(0);
    for (int c = 0; c < HDIM / 32; c++) {
        __syncthreads();
        *(uint4*)(sm + GU_AHI + aSt)      = rah[0];
        *(uint4*)(sm + GU_AHI + aSt + 16) = rah[1];
        *(uint4*)(sm + GU_ALO + aSt)      = ral[0];
        *(uint4*)(sm + GU_ALO + aSt + 16) = ral[1];
        uint4 h, l;
        split8(rbg[0], rbg[1], h, l);
        *(uint4*)(sm + GU_BGH + bSt) = h;
        *(uint4*)(sm + GU_BGL + bSt) = l;
        split8(rbu[0], rbu[1], h, l);
        *(uint4*)(sm + GU_BUH + bSt) = h;
        *(uint4*)(sm + GU_BUL + bSt) = l;
        __syncthreads();
        if (c + 1 < HDIM / 32) GU_LOAD((c + 1) * 32);

#pragma unroll
        for (int ks = 0; ks < 2; ks++) {
            uint32_t ah[4][4], al[4][4];
#pragma unroll
            for (int i = 0; i < 4; i++) {
                LDSM4(ah[i], aHiB + i * (16 * LDS_ROW) + ks * 32);
                LDSM4(al[i], aLoB + i * (16 * LDS_ROW) + ks * 32);
            }
            uint32_t bgh[2][2], bgl[2][2], buh[2][2], bul[2][2];
#pragma unroll
            for (int j = 0; j < 2; j++) {
                LDSM2(bgh[j], bGH + j * (8 * LDS_ROW) + ks * 32);
                LDSM2(bgl[j], bGL + j * (8 * LDS_ROW) + ks * 32);
                LDSM2(buh[j], bUH + j * (8 * LDS_ROW) + ks * 32);
                LDSM2(bul[j], bUL + j * (8 * LDS_ROW) + ks * 32);
            }
#pragma unroll
            for (int i = 0; i < 4; i++)
#pragma unroll
                for (int j = 0; j < 2; j++) {
                    MMA(accg[i][j], ah[i], bgh[j]);
                    MMA(accg[i][j], ah[i], bgl[j]);
                    MMA(accg[i][j], al[i], bgh[j]);
                    MMA(accu[i][j], ah[i], buh[j]);
                    MMA(accu[i][j], ah[i], bul[j]);
                    MMA(accu[i][j], al[i], buh[j]);
                }
        }
    }

    // epilogue: silu(g)*u, split to bf16 planes
    const int mrow = wm * 64 + (lane >> 2);
    const int col0 = n0 + wn * 16 + (lane & 3) * 2;
#pragma unroll
    for (int i = 0; i < 4; i++)
#pragma unroll
        for (int j = 0; j < 2; j++) {
            int col = col0 + j * 8;
#pragma unroll
            for (int half = 0; half < 2; half++) {
                int r = row0 + mrow + i * 16 + half * 8;
                if (r < nrows) {
                    float gv0 = accg[i][j][half * 2],     uv0 = accu[i][j][half * 2];
                    float gv1 = accg[i][j][half * 2 + 1], uv1 = accu[i][j][half * 2 + 1];
                    float a0 = (gv0 / (1.f + __expf(-gv0))) * uv0;
                    float a1 = (gv1 / (1.f + __expf(-gv1))) * uv1;
                    uint32_t hi, lo;
                    split2(a0, a1, hi, lo);
                    size_t idx = ((size_t)eSlot * NTOK + r) * MDIM + col;
                    *(uint32_t*)(g_ahi + idx) = hi;
                    *(uint32_t*)(g_alo + idx) = lo;
                }
            }
        }
#undef GU_LOAD
}

// =======================================================================
// down: y[tok] += w * (act @ Wd^T)   (tile 128x128, K chunk 32)
// =======================================================================
#define DN_AHI 0
#define DN_ALO 10240
#define DN_BH  20480
#define DN_BL  30720
#define DN_TOK 40960
#define DN_WTS 41472
#define DN_SM  41984

template<bool SHARED>
__global__ __launch_bounds__(256)
void down_mma(const float* __restrict__ wdown, float* __restrict__ y) {
    __shared__ __align__(16) char sm[DN_SM];
    const int e = SHARED ? 0 : blockIdx.z;
    const int eSlot = SHARED ? NEXP : blockIdx.z;
    const int nrows = SHARED ? NTOK : g_cnt[e];
    const int row0 = blockIdx.x * 128;
    if (row0 >= nrows) return;
    const int h0 = blockIdx.y * 128;
    const float* wd = wdown + (SHARED ? 0 : (size_t)e * HDIM * MDIM);

    const int tid = threadIdx.x, wid = tid >> 5, lane = tid & 31;
    int* toks = (int*)(sm + DN_TOK);
    float* wts = (float*)(sm + DN_WTS);
    if (tid < 128) {
        int r = row0 + tid;
        if (r < nrows) {
            toks[tid] = SHARED ? r : g_tok[e * NTOK + r];
            wts[tid]  = SHARED ? 1.f : g_wt[e * NTOK + r];
        } else { toks[tid] = 0; wts[tid] = 0.f; }
    }
    __syncthreads();

    const int arow = tid >> 1, aseg = tid & 1;
    const __nv_bfloat16* aph = g_ahi + ((size_t)eSlot * NTOK + row0 + arow) * MDIM + aseg * 16;
    const __nv_bfloat16* apl = g_alo + ((size_t)eSlot * NTOK + row0 + arow) * MDIM + aseg * 16;
    const float* bp = wd + (size_t)(h0 + arow) * MDIM + aseg * 16;

    uint4 rah[2], ral[2];
    float4 rb[4];
#define DN_LOAD(k0) do {                                                   \
    rah[0] = *(const uint4*)(aph + (k0));  rah[1] = *(const uint4*)(aph + (k0) + 8); \
    ral[0] = *(const uint4*)(apl + (k0));  ral[1] = *(const uint4*)(apl + (k0) + 8); \
    rb[0] = *(const float4*)(bp + (k0));      rb[1] = *(const float4*)(bp + (k0) + 4);  \
    rb[2] = *(const float4*)(bp + (k0) + 8);  rb[3] = *(const float4*)(bp + (k0) + 12); \
} while (0)

    const uint32_t sb = smem_u32(sm);
    const int wm = wid & 1, wn = wid >> 1;   // warp tile 64 x 32
    const uint32_t aOffL = (lane & 15) * LDS_ROW + (lane >> 4) * 16;
    const uint32_t bOffL = (lane & 7) * LDS_ROW + ((lane >> 3) & 1) * 16;
    const uint32_t aHiB = sb + DN_AHI + (wm * 64) * LDS_ROW + aOffL;
    const uint32_t aLoB = sb + DN_ALO + (wm * 64) * LDS_ROW + aOffL;
    const uint32_t bHB = sb + DN_BH + (wn * 32) * LDS_ROW + bOffL;
    const uint32_t bLB = sb + DN_BL + (wn * 32) * LDS_ROW + bOffL;

    const uint32_t aSt = arow * LDS_ROW + aseg * 32;

    float acc[4][4][4] = {};

    DN_LOAD(0);
    for (int c = 0; c < MDIM / 32; c++) {
        __syncthreads();
        *(uint4*)(sm + DN_AHI + aSt)      = rah[0];
        *(uint4*)(sm + DN_AHI + aSt + 16) = rah[1];
        *(uint4*)(sm + DN_ALO + aSt)      = ral[0];
        *(uint4*)(sm + DN_ALO + aSt + 16) = ral[1];
        uint4 h, l;
        split8(rb[0], rb[1], h, l);
        *(uint4*)(sm + DN_BH + aSt) = h;
        *(uint4*)(sm + DN_BL + aSt) = l;
        split8(rb[2], rb[3], h, l);
        *(uint4*)(sm + DN_BH + aSt + 16) = h;
        *(uint4*)(sm + DN_BL + aSt + 16) = l;
        __syncthreads();
        if (c + 1 < MDIM / 32) DN_LOAD((c + 1) * 32);

#pragma unroll
        for (int ks = 0; ks < 2; ks++) {
            uint32_t ah[4][4], al[4][4];
#pragma unroll
            for (int i = 0; i < 4; i++) {
                LDSM4(ah[i], aHiB + i * (16 * LDS_ROW) + ks * 32);
                LDSM4(al[i], aLoB + i * (16 * LDS_ROW) + ks * 32);
            }
            uint32_t bh[4][2], bl[4][2];
#pragma unroll
            for (int j = 0; j < 4; j++) {
                LDSM2(bh[j], bHB + j * (8 * LDS_ROW) + ks * 32);
                LDSM2(bl[j], bLB + j * (8 * LDS_ROW) + ks * 32);
            }
#pragma unroll
            for (int i = 0; i < 4; i++)
#pragma unroll
                for (int j = 0; j < 4; j++) {
                    MMA(acc[i][j], ah[i], bh[j]);
                    MMA(acc[i][j], ah[i], bl[j]);
                    MMA(acc[i][j], al[i], bh[j]);
                }
        }
    }

    // epilogue: weighted atomic scatter
    const int mrow = wm * 64 + (lane >> 2);
    const int col0 = h0 + wn * 32 + (lane & 3) * 2;
#pragma unroll
    for (int i = 0; i < 4; i++)
#pragma unroll
        for (int half = 0; half < 2; half++) {
            int rl = mrow + i * 16 + half * 8;
            int r = row0 + rl;
            if (r < nrows) {
                float w = wts[rl];
                int tok = toks[rl];
                float* yp = y + (size_t)tok * HDIM;
#pragma unroll
                for (int j = 0; j < 4; j++) {
                    int col = col0 + j * 8;
                    atomicAdd(&yp[col],     acc[i][j][half * 2]     * w);
                    atomicAdd(&yp[col + 1], acc[i][j][half * 2 + 1] * w);
                }
            }
        }
#undef DN_LOAD
}

// ---------------- aux loss ----------------
__global__ void aux_kernel(float* __restrict__ p) {
    float a = 0.f;
#pragma unroll
    for (int e = 0; e < NEXP; e++) {
        float ce = (float)g_cnt[e] * ((float)NEXP / (float)(NTOK * 2));
        float pi = g_pisum[e] / (float)NTOK;
        a += ce * pi;
    }
    *p = a * 0.001f;
}

// ---------------- launch ----------------
extern "C" void kernel_launch(void* const* d_in, const int* in_sizes, int n_in,
                              void* d_out, int out_size) {
    (void)in_sizes; (void)n_in;
    const float* x   = (const float*)d_in[0];
    const float* gw  = (const float*)d_in[1];
    const float* wgt = (const float*)d_in[2];
    const float* wup = (const float*)d_in[3];
    const float* wdn = (const float*)d_in[4];
    const float* shg = (const float*)d_in[5];
    const float* shu = (const float*)d_in[6];
    const float* shd = (const float*)d_in[7];
    float* y = (float*)d_out;

    zero_kernel<<<(NTOK * HDIM + 255) / 256, 256>>>(y);
    gate_kernel<<<NTOK, 256>>>(x, gw);
    xconv_kernel<<<(NTOK * HDIM + 255) / 256, 256>>>(x);

    gateup_mma<false><<<dim3(NTOK / 128, MDIM / 64, NEXP), 256>>>(wgt, wup);
    gateup_mma<true ><<<dim3(NTOK / 128, MDIM / 64, 1),    256>>>(shg, shu);

    down_mma<false><<<dim3(NTOK / 128, HDIM / 128, NEXP), 256>>>(wdn, y);
    down_mma<true ><<<dim3(NTOK / 128, HDIM / 128, 1),    256>>>(shd, y);

    if (out_size > NTOK * HDIM)
        aux_kernel<<<1, 1>>>(y + NTOK * HDIM);
}

// round 4
// speedup vs baseline: 1.9892x; 1.3236x over previous
#include <cuda_runtime.h>
#include <cuda_bf16.h>
#include <cstdint>

#define HDIM 2048
#define MDIM 1408
#define NEXP 8
#define NTOK 1024

// ---------------- device scratch ----------------
__device__ __nv_bfloat16 g_xhi[NTOK * HDIM];
__device__ __nv_bfloat16 g_xlo[NTOK * HDIM];
__device__ __nv_bfloat16 g_ahi[(NEXP + 1) * NTOK * MDIM];
__device__ __nv_bfloat16 g_alo[(NEXP + 1) * NTOK * MDIM];
__device__ int   g_tok[NEXP * NTOK];
__device__ float g_wt[NEXP * NTOK];
__device__ int   g_cnt[NEXP];
__device__ float g_pisum[NEXP];

// ---------------- helpers ----------------
__device__ __forceinline__ uint32_t smem_u32(const void* p) {
    uint32_t a;
    asm("{ .reg .u64 t; cvta.to.shared.u64 t, %1; cvt.u32.u64 %0, t; }" : "=r"(a) : "l"(p));
    return a;
}
__device__ __forceinline__ void cp16(uint32_t dst, const void* src) {
    asm volatile("cp.async.cg.shared.global [%0], [%1], 16;" :: "r"(dst), "l"(src));
}
#define CP_COMMIT() asm volatile("cp.async.commit_group;" ::: "memory")
#define CP_WAIT0()  asm volatile("cp.async.wait_group 0;" ::: "memory")

#define LDSM4(r, addr)                                                                       \
    asm volatile("ldmatrix.sync.aligned.m8n8.x4.shared.b16 {%0,%1,%2,%3}, [%4];"             \
                 : "=r"((r)[0]), "=r"((r)[1]), "=r"((r)[2]), "=r"((r)[3]) : "r"(addr))
#define LDSM2(r, addr)                                                                       \
    asm volatile("ldmatrix.sync.aligned.m8n8.x2.shared.b16 {%0,%1}, [%2];"                   \
                 : "=r"((r)[0]), "=r"((r)[1]) : "r"(addr))
#define MMA(c, a, b)                                                                         \
    asm volatile("mma.sync.aligned.m16n8k16.row.col.f32.bf16.bf16.f32 "                      \
                 "{%0,%1,%2,%3},{%4,%5,%6,%7},{%8,%9},{%0,%1,%2,%3};"                        \
                 : "+f"((c)[0]), "+f"((c)[1]), "+f"((c)[2]), "+f"((c)[3])                    \
                 : "r"((a)[0]), "r"((a)[1]), "r"((a)[2]), "r"((a)[3]), "r"((b)[0]), "r"((b)[1]))

__device__ __forceinline__ void split2(float a, float b, uint32_t& hi, uint32_t& lo) {
    __nv_bfloat16 ha = __float2bfloat16(a), hb = __float2bfloat16(b);
    float ra = a - __bfloat162float(ha), rb = b - __bfloat162float(hb);
    __nv_bfloat16 la = __float2bfloat16(ra), lb = __float2bfloat16(rb);
    __nv_bfloat162 hp; hp.x = ha; hp.y = hb;
    __nv_bfloat162 lp; lp.x = la; lp.y = lb;
    hi = *reinterpret_cast<uint32_t*>(&hp);
    lo = *reinterpret_cast<uint32_t*>(&lp);
}
__device__ __forceinline__ void split8(const float4& a, const float4& b, uint4& hi, uint4& lo) {
    split2(a.x, a.y, hi.x, lo.x);
    split2(a.z, a.w, hi.y, lo.y);
    split2(b.x, b.y, hi.z, lo.z);
    split2(b.z, b.w, hi.w, lo.w);
}

#define LDS_ROW 80   // 32 bf16 + 16B pad -> conflict-free ldmatrix

// ---------------- init ----------------
__global__ void zero_kernel(float* __restrict__ y) {
    int i = blockIdx.x * blockDim.x + threadIdx.x;
    if (i < NTOK * HDIM) y[i] = 0.f;
    if (i < NEXP) { g_cnt[i] = 0; g_pisum[i] = 0.f; }
}

__global__ void xconv_kernel(const float* __restrict__ x) {
    int i = blockIdx.x * blockDim.x + threadIdx.x;
    if (i < NTOK * HDIM) {
        float v = x[i];
        __nv_bfloat16 h = __float2bfloat16(v);
        __nv_bfloat16 l = __float2bfloat16(v - __bfloat162float(h));
        g_xhi[i] = h; g_xlo[i] = l;
    }
}

// ---------------- gate ----------------
__global__ __launch_bounds__(256)
void gate_kernel(const float* __restrict__ x, const float* __restrict__ gw) {
    const int t = blockIdx.x;
    const float* xr = x + (size_t)t * HDIM;
    float acc[NEXP];
#pragma unroll
    for (int e = 0; e < NEXP; e++) acc[e] = 0.f;
    for (int h = threadIdx.x; h < HDIM; h += 256) {
        float xv = xr[h];
#pragma unroll
        for (int e = 0; e < NEXP; e++) acc[e] = fmaf(xv, gw[e * HDIM + h], acc[e]);
    }
#pragma unroll
    for (int e = 0; e < NEXP; e++)
        for (int o = 16; o > 0; o >>= 1) acc[e] += __shfl_down_sync(0xffffffffu, acc[e], o);

    __shared__ float red[8][NEXP];
    int warp = threadIdx.x >> 5, lane = threadIdx.x & 31;
    if (lane == 0) {
#pragma unroll
        for (int e = 0; e < NEXP; e++) red[warp][e] = acc[e];
    }
    __syncthreads();
    if (threadIdx.x == 0) {
        float lg[NEXP];
#pragma unroll
        for (int e = 0; e < NEXP; e++) {
            float s = 0.f;
            for (int w = 0; w < 8; w++) s += red[w][e];
            lg[e] = s;
        }
        float mx = lg[0];
#pragma unroll
        for (int e = 1; e < NEXP; e++) mx = fmaxf(mx, lg[e]);
        float p[NEXP]; float den = 0.f;
#pragma unroll
        for (int e = 0; e < NEXP; e++) { p[e] = __expf(lg[e] - mx); den += p[e]; }
#pragma unroll
        for (int e = 0; e < NEXP; e++) p[e] /= den;
#pragma unroll
        for (int e = 0; e < NEXP; e++) atomicAdd(&g_pisum[e], p[e]);
        int i1 = 0;
#pragma unroll
        for (int e = 1; e < NEXP; e++) if (p[e] > p[i1]) i1 = e;
        int i2 = -1;
#pragma unroll
        for (int e = 0; e < NEXP; e++) {
            if (e == i1) continue;
            if (i2 < 0 || p[e] > p[i2]) i2 = e;
        }
        float w1 = p[i1], w2 = p[i2];
        float s2 = w1 + w2 + 1e-20f;
        w1 /= s2; w2 /= s2;
        int pos1 = atomicAdd(&g_cnt[i1], 1);
        g_tok[i1 * NTOK + pos1] = t; g_wt[i1 * NTOK + pos1] = w1;
        int pos2 = atomicAdd(&g_cnt[i2], 1);
        g_tok[i2 * NTOK + pos2] = t; g_wt[i2 * NTOK + pos2] = w2;
    }
}

// =======================================================================
// gateup: act = silu(X Wg^T) * (X Wu^T)   tile 128x64, K chunk 32, 2-stage
// =======================================================================
#define STAGE  40960
#define GU_AHI 0
#define GU_ALO 10240
#define GU_BGH 20480
#define GU_BGL 25600
#define GU_BUH 30720
#define GU_BUL 35840
#define GU_TOK 81920
#define GU_SM  82432

template<bool SHARED>
__global__ __launch_bounds__(256)
void gateup_mma(const float* __restrict__ wgate, const float* __restrict__ wup) {
    extern __shared__ __align__(128) char sm[];
    const int e = SHARED ? 0 : blockIdx.z;
    const int eSlot = SHARED ? NEXP : blockIdx.z;
    const int nrows = SHARED ? NTOK : g_cnt[e];
    const int row0 = blockIdx.x * 128;
    if (row0 >= nrows) return;
    const int n0 = blockIdx.y * 64;
    const float* wg = wgate + (SHARED ? 0 : (size_t)e * MDIM * HDIM);
    const float* wu = wup   + (SHARED ? 0 : (size_t)e * MDIM * HDIM);

    const int tid = threadIdx.x, wid = tid >> 5, lane = tid & 31;
    int* toks = (int*)(sm + GU_TOK);
    if (tid < 128) {
        int r = row0 + tid;
        toks[tid] = (r < nrows) ? (SHARED ? r : g_tok[e * NTOK + r]) : 0;
    }
    __syncthreads();

    const uint32_t sb = smem_u32(sm);

    // A cp.async mapping: 2 thr/row, 16 bf16 (32B) per thread per plane
    const int arow = tid >> 1, aseg = tid & 1;
    const __nv_bfloat16* aph = g_xhi + (size_t)toks[arow] * HDIM + aseg * 16;
    const __nv_bfloat16* apl = g_xlo + (size_t)toks[arow] * HDIM + aseg * 16;
    const uint32_t aDstH = sb + GU_AHI + arow * LDS_ROW + aseg * 32;
    const uint32_t aDstL = sb + GU_ALO + arow * LDS_ROW + aseg * 32;
#define GU_CPA(c, stg) do { uint32_t o = (stg) * STAGE;                     \
    cp16(aDstH + o,      aph + (c) * 32);                                   \
    cp16(aDstH + o + 16, aph + (c) * 32 + 8);                               \
    cp16(aDstL + o,      apl + (c) * 32);                                   \
    cp16(aDstL + o + 16, apl + (c) * 32 + 8); } while (0)

    // B register path: 4 thr/row, 8 fp32 per thread
    const int brow = tid >> 2, bseg = tid & 3;
    const float* gp = wg + (size_t)(n0 + brow) * HDIM + bseg * 8;
    const float* up = wu + (size_t)(n0 + brow) * HDIM + bseg * 8;
    float4 rbg[2], rbu[2];
#define GU_BLD(k0) do {                                                     \
    rbg[0] = *(const float4*)(gp + (k0));  rbg[1] = *(const float4*)(gp + (k0) + 4); \
    rbu[0] = *(const float4*)(up + (k0));  rbu[1] = *(const float4*)(up + (k0) + 4); \
} while (0)
    const uint32_t bSt = brow * LDS_ROW + bseg * 16;

    // compute fragment bases
    const int wm = wid & 1, wn = wid >> 1;   // warp tile 64x16
    const uint32_t aOffL = (lane & 15) * LDS_ROW + (lane >> 4) * 16;
    const uint32_t bOffL = (lane & 7) * LDS_ROW + ((lane >> 3) & 1) * 16;
    const uint32_t aHiB = sb + GU_AHI + (wm * 64) * LDS_ROW + aOffL;
    const uint32_t aLoB = sb + GU_ALO + (wm * 64) * LDS_ROW + aOffL;
    const uint32_t bGH = sb + GU_BGH + (wn * 16) * LDS_ROW + bOffL;
    const uint32_t bGL = sb + GU_BGL + (wn * 16) * LDS_ROW + bOffL;
    const uint32_t bUH = sb + GU_BUH + (wn * 16) * LDS_ROW + bOffL;
    const uint32_t bUL = sb + GU_BUL + (wn * 16) * LDS_ROW + bOffL;

    float accg[4][2][4] = {}, accu[4][2][4] = {};

    GU_CPA(0, 0); CP_COMMIT();
    GU_BLD(0);

    const int NC = HDIM / 32;
    for (int c = 0; c < NC; c++) {
        const uint32_t so = (c & 1) * STAGE;
        // store B chunk c (split fp32 -> bf16 hi/lo)
        {
            uint4 h, l;
            split8(rbg[0], rbg[1], h, l);
            *(uint4*)(sm + GU_BGH + so + bSt) = h;
            *(uint4*)(sm + GU_BGL + so + bSt) = l;
            split8(rbu[0], rbu[1], h, l);
            *(uint4*)(sm + GU_BUH + so + bSt) = h;
            *(uint4*)(sm + GU_BUL + so + bSt) = l;
        }
        CP_WAIT0();
        __syncthreads();
        if (c + 1 < NC) {
            GU_CPA(c + 1, (c & 1) ^ 1); CP_COMMIT();
            GU_BLD((c + 1) * 32);
        }
#pragma unroll
        for (int ks = 0; ks < 2; ks++) {
            uint32_t ah[4][4], al[4][4];
#pragma unroll
            for (int i = 0; i < 4; i++) {
                LDSM4(ah[i], aHiB + so + i * (16 * LDS_ROW) + ks * 32);
                LDSM4(al[i], aLoB + so + i * (16 * LDS_ROW) + ks * 32);
            }
            uint32_t bgh[2][2], bgl[2][2], buh[2][2], bul[2][2];
#pragma unroll
            for (int j = 0; j < 2; j++) {
                LDSM2(bgh[j], bGH + so + j * (8 * LDS_ROW) + ks * 32);
                LDSM2(bgl[j], bGL + so + j * (8 * LDS_ROW) + ks * 32);
                LDSM2(buh[j], bUH + so + j * (8 * LDS_ROW) + ks * 32);
                LDSM2(bul[j], bUL + so + j * (8 * LDS_ROW) + ks * 32);
            }
#pragma unroll
            for (int i = 0; i < 4; i++)
#pragma unroll
                for (int j = 0; j < 2; j++) {
                    MMA(accg[i][j], ah[i], bgh[j]);
                    MMA(accg[i][j], ah[i], bgl[j]);
                    MMA(accg[i][j], al[i], bgh[j]);
                    MMA(accu[i][j], ah[i], buh[j]);
                    MMA(accu[i][j], ah[i], bul[j]);
                    MMA(accu[i][j], al[i], buh[j]);
                }
        }
    }

    // epilogue: silu(g)*u -> bf16 planes
    const int mrow = wm * 64 + (lane >> 2);
    const int col0 = n0 + wn * 16 + (lane & 3) * 2;
#pragma unroll
    for (int i = 0; i < 4; i++)
#pragma unroll
        for (int j = 0; j < 2; j++) {
            int col = col0 + j * 8;
#pragma unroll
            for (int half = 0; half < 2; half++) {
                int r = row0 + mrow + i * 16 + half * 8;
                if (r < nrows) {
                    float gv0 = accg[i][j][half * 2],     uv0 = accu[i][j][half * 2];
                    float gv1 = accg[i][j][half * 2 + 1], uv1 = accu[i][j][half * 2 + 1];
                    float a0 = (gv0 / (1.f + __expf(-gv0))) * uv0;
                    float a1 = (gv1 / (1.f + __expf(-gv1))) * uv1;
                    uint32_t hi, lo;
                    split2(a0, a1, hi, lo);
                    size_t idx = ((size_t)eSlot * NTOK + r) * MDIM + col;
                    *(uint32_t*)(g_ahi + idx) = hi;
                    *(uint32_t*)(g_alo + idx) = lo;
                }
            }
        }
#undef GU_CPA
#undef GU_BLD
}

// =======================================================================
// down: y[tok] += w * (act @ Wd^T)   tile 128x128, K chunk 32, 2-stage
// =======================================================================
#define DN_AHI 0
#define DN_ALO 10240
#define DN_BH  20480
#define DN_BL  30720
#define DN_TOK 81920
#define DN_WTS 82432
#define DN_SM  82944

template<bool SHARED>
__global__ __launch_bounds__(256)
void down_mma(const float* __restrict__ wdown, float* __restrict__ y) {
    extern __shared__ __align__(128) char sm[];
    const int e = SHARED ? 0 : blockIdx.z;
    const int eSlot = SHARED ? NEXP : blockIdx.z;
    const int nrows = SHARED ? NTOK : g_cnt[e];
    const int row0 = blockIdx.x * 128;
    if (row0 >= nrows) return;
    const int h0 = blockIdx.y * 128;
    const float* wd = wdown + (SHARED ? 0 : (size_t)e * HDIM * MDIM);

    const int tid = threadIdx.x, wid = tid >> 5, lane = tid & 31;
    int* toks = (int*)(sm + DN_TOK);
    float* wts = (float*)(sm + DN_WTS);
    if (tid < 128) {
        int r = row0 + tid;
        if (r < nrows) {
            toks[tid] = SHARED ? r : g_tok[e * NTOK + r];
            wts[tid]  = SHARED ? 1.f : g_wt[e * NTOK + r];
        } else { toks[tid] = 0; wts[tid] = 0.f; }
    }
    __syncthreads();

    const uint32_t sb = smem_u32(sm);

    // A via cp.async (activations bf16 planes, slot rows contiguous)
    const int arow = tid >> 1, aseg = tid & 1;
    const __nv_bfloat16* aph = g_ahi + ((size_t)eSlot * NTOK + row0 + arow) * MDIM + aseg * 16;
    const __nv_bfloat16* apl = g_alo + ((size_t)eSlot * NTOK + row0 + arow) * MDIM + aseg * 16;
    const uint32_t aDstH = sb + DN_AHI + arow * LDS_ROW + aseg * 32;
    const uint32_t aDstL = sb + DN_ALO + arow * LDS_ROW + aseg * 32;
#define DN_CPA(c, stg) do { uint32_t o = (stg) * STAGE;                     \
    cp16(aDstH + o,      aph + (c) * 32);                                   \
    cp16(aDstH + o + 16, aph + (c) * 32 + 8);                               \
    cp16(aDstL + o,      apl + (c) * 32);                                   \
    cp16(aDstL + o + 16, apl + (c) * 32 + 8); } while (0)

    // B register path: 2 thr/row, 16 fp32 per thread
    const float* bp = wd + (size_t)(h0 + arow) * MDIM + aseg * 16;
    float4 rb[4];
#define DN_BLD(k0) do {                                                     \
    rb[0] = *(const float4*)(bp + (k0));      rb[1] = *(const float4*)(bp + (k0) + 4);  \
    rb[2] = *(const float4*)(bp + (k0) + 8);  rb[3] = *(const float4*)(bp + (k0) + 12); \
} while (0)
    const uint32_t bSt = arow * LDS_ROW + aseg * 32;

    const int wm = wid & 1, wn = wid >> 1;   // warp tile 64x32
    const uint32_t aOffL = (lane & 15) * LDS_ROW + (lane >> 4) * 16;
    const uint32_t bOffL = (lane & 7) * LDS_ROW + ((lane >> 3) & 1) * 16;
    const uint32_t aHiB = sb + DN_AHI + (wm * 64) * LDS_ROW + aOffL;
    const uint32_t aLoB = sb + DN_ALO + (wm * 64) * LDS_ROW + aOffL;
    const uint32_t bHB = sb + DN_BH + (wn * 32) * LDS_ROW + bOffL;
    const uint32_t bLB = sb + DN_BL + (wn * 32) * LDS_ROW + bOffL;

    float acc[4][4][4] = {};

    DN_CPA(0, 0); CP_COMMIT();
    DN_BLD(0);

    const int NC = MDIM / 32;
    for (int c = 0; c < NC; c++) {
        const uint32_t so = (c & 1) * STAGE;
        {
            uint4 h, l;
            split8(rb[0], rb[1], h, l);
            *(uint4*)(sm + DN_BH + so + bSt) = h;
            *(uint4*)(sm + DN_BL + so + bSt) = l;
            split8(rb[2], rb[3], h, l);
            *(uint4*)(sm + DN_BH + so + bSt + 16) = h;
            *(uint4*)(sm + DN_BL + so + bSt + 16) = l;
        }
        CP_WAIT0();
        __syncthreads();
        if (c + 1 < NC) {
            DN_CPA(c + 1, (c & 1) ^ 1); CP_COMMIT();
            DN_BLD((c + 1) * 32);
        }
#pragma unroll
        for (int ks = 0; ks < 2; ks++) {
            uint32_t ah[4][4], al[4][4];
#pragma unroll
            for (int i = 0; i < 4; i++) {
                LDSM4(ah[i], aHiB + so + i * (16 * LDS_ROW) + ks * 32);
                LDSM4(al[i], aLoB + so + i * (16 * LDS_ROW) + ks * 32);
            }
            uint32_t bh[4][2], bl[4][2];
#pragma unroll
            for (int j = 0; j < 4; j++) {
                LDSM2(bh[j], bHB + so + j * (8 * LDS_ROW) + ks * 32);
                LDSM2(bl[j], bLB + so + j * (8 * LDS_ROW) + ks * 32);
            }
#pragma unroll
            for (int i = 0; i < 4; i++)
#pragma unroll
                for (int j = 0; j < 4; j++) {
                    MMA(acc[i][j], ah[i], bh[j]);
                    MMA(acc[i][j], ah[i], bl[j]);
                    MMA(acc[i][j], al[i], bh[j]);
                }
        }
    }

    // epilogue: weighted atomic scatter
    const int mrow = wm * 64 + (lane >> 2);
    const int col0 = h0 + wn * 32 + (lane & 3) * 2;
#pragma unroll
    for (int i = 0; i < 4; i++)
#pragma unroll
        for (int half = 0; half < 2; half++) {
            int rl = mrow + i * 16 + half * 8;
            int r = row0 + rl;
            if (r < nrows) {
                float w = wts[rl];
                int tok = toks[rl];
                float* yp = y + (size_t)tok * HDIM;
#pragma unroll
                for (int j = 0; j < 4; j++) {
                    int col = col0 + j * 8;
                    atomicAdd(&yp[col],     acc[i][j][half * 2]     * w);
                    atomicAdd(&yp[col + 1], acc[i][j][half * 2 + 1] * w);
                }
            }
        }
#undef DN_CPA
#undef DN_BLD
}

// ---------------- aux loss ----------------
__global__ void aux_kernel(float* __restrict__ p) {
    float a = 0.f;
#pragma unroll
    for (int e = 0; e < NEXP; e++) {
        float ce = (float)g_cnt[e] * ((float)NEXP / (float)(NTOK * 2));
        float pi = g_pisum[e] / (float)NTOK;
        a += ce * pi;
    }
    *p = a * 0.001f;
}

// ---------------- launch ----------------
extern "C" void kernel_launch(void* const* d_in, const int* in_sizes, int n_in,
                              void* d_out, int out_size) {
    (void)in_sizes; (void)n_in;
    const float* x   = (const float*)d_in[0];
    const float* gw  = (const float*)d_in[1];
    const float* wgt = (const float*)d_in[2];
    const float* wup = (const float*)d_in[3];
    const float* wdn = (const float*)d_in[4];
    const float* shg = (const float*)d_in[5];
    const float* shu = (const float*)d_in[6];
    const float* shd = (const float*)d_in[7];
    float* y = (float*)d_out;

    cudaFuncSetAttribute(gateup_mma<false>, cudaFuncAttributeMaxDynamicSharedMemorySize, GU_SM);
    cudaFuncSetAttribute(gateup_mma<true>,  cudaFuncAttributeMaxDynamicSharedMemorySize, GU_SM);
    cudaFuncSetAttribute(down_mma<false>,   cudaFuncAttributeMaxDynamicSharedMemorySize, DN_SM);
    cudaFuncSetAttribute(down_mma<true>,    cudaFuncAttributeMaxDynamicSharedMemorySize, DN_SM);

    zero_kernel<<<(NTOK * HDIM + 255) / 256, 256>>>(y);
    gate_kernel<<<NTOK, 256>>>(x, gw);
    xconv_kernel<<<(NTOK * HDIM + 255) / 256, 256>>>(x);

    gateup_mma<false><<<dim3(NTOK / 128, MDIM / 64, NEXP), 256, GU_SM>>>(wgt, wup);
    gateup_mma<true ><<<dim3(NTOK / 128, MDIM / 64, 1),    256, GU_SM>>>(shg, shu);

    down_mma<false><<<dim3(NTOK / 128, HDIM / 128, NEXP), 256, DN_SM>>>(wdn, y);
    down_mma<true ><<<dim3(NTOK / 128, HDIM / 128, 1),    256, DN_SM>>>(shd, y);

    if (out_size > NTOK * HDIM)
        aux_kernel<<<1, 1>>>(y + NTOK * HDIM);
}

// round 6
// speedup vs baseline: 2.2240x; 1.1181x over previous
#include <cuda_runtime.h>
#include <cuda_bf16.h>
#include <cstdint>

#define HDIM 2048
#define MDIM 1408
#define NEXP 8
#define NTOK 1024

// ---------------- device scratch ----------------
__device__ __nv_bfloat16 g_xhi[NTOK * HDIM];
__device__ __nv_bfloat16 g_xlo[NTOK * HDIM];
__device__ __nv_bfloat16 g_ahi[(NEXP + 1) * NTOK * MDIM];
__device__ __nv_bfloat16 g_alo[(NEXP + 1) * NTOK * MDIM];
// weight bf16 hi/lo planes; slot NEXP = shared expert
__device__ __nv_bfloat16 g_wghi[(NEXP + 1) * MDIM * HDIM];
__device__ __nv_bfloat16 g_wglo[(NEXP + 1) * MDIM * HDIM];
__device__ __nv_bfloat16 g_wuhi[(NEXP + 1) * MDIM * HDIM];
__device__ __nv_bfloat16 g_wulo[(NEXP + 1) * MDIM * HDIM];
__device__ __nv_bfloat16 g_wdhi[(NEXP + 1) * HDIM * MDIM];
__device__ __nv_bfloat16 g_wdlo[(NEXP + 1) * HDIM * MDIM];
__device__ int   g_tok[NEXP * NTOK];
__device__ float g_wt[NEXP * NTOK];
__device__ int   g_cnt[NEXP];
__device__ float g_pisum[NEXP];

// ---------------- helpers ----------------
__device__ __forceinline__ uint32_t smem_u32(const void* p) {
    uint32_t a;
    asm("{ .reg .u64 t; cvta.to.shared.u64 t, %1; cvt.u32.u64 %0, t; }" : "=r"(a) : "l"(p));
    return a;
}
__device__ __forceinline__ void cp16(uint32_t dst, const void* src) {
    asm volatile("cp.async.cg.shared.global [%0], [%1], 16;" :: "r"(dst), "l"(src));
}
#define CP_COMMIT() asm volatile("cp.async.commit_group;" ::: "memory")
#define CP_WAIT0()  asm volatile("cp.async.wait_group 0;" ::: "memory")

#define LDSM4(r, addr)                                                                       \
    asm volatile("ldmatrix.sync.aligned.m8n8.x4.shared.b16 {%0,%1,%2,%3}, [%4];"             \
                 : "=r"((r)[0]), "=r"((r)[1]), "=r"((r)[2]), "=r"((r)[3]) : "r"(addr))
#define LDSM2(r, addr)                                                                       \
    asm volatile("ldmatrix.sync.aligned.m8n8.x2.shared.b16 {%0,%1}, [%2];"                   \
                 : "=r"((r)[0]), "=r"((r)[1]) : "r"(addr))
#define MMA(c, a, b)                                                                         \
    asm volatile("mma.sync.aligned.m16n8k16.row.col.f32.bf16.bf16.f32 "                      \
                 "{%0,%1,%2,%3},{%4,%5,%6,%7},{%8,%9},{%0,%1,%2,%3};"                        \
                 : "+f"((c)[0]), "+f"((c)[1]), "+f"((c)[2]), "+f"((c)[3])                    \
                 : "r"((a)[0]), "r"((a)[1]), "r"((a)[2]), "r"((a)[3]), "r"((b)[0]), "r"((b)[1]))

__device__ __forceinline__ void split2(float a, float b, uint32_t& hi, uint32_t& lo) {
    __nv_bfloat16 ha = __float2bfloat16(a), hb = __float2bfloat16(b);
    float ra = a - __bfloat162float(ha), rb = b - __bfloat162float(hb);
    __nv_bfloat16 la = __float2bfloat16(ra), lb = __float2bfloat16(rb);
    __nv_bfloat162 hp; hp.x = ha; hp.y = hb;
    __nv_bfloat162 lp; lp.x = la; lp.y = lb;
    hi = *reinterpret_cast<uint32_t*>(&hp);
    lo = *reinterpret_cast<uint32_t*>(&lp);
}

#define LDS_ROW 80   // 32 bf16 + 16B pad -> conflict-free ldmatrix

// ---------------- init / conversions ----------------
__global__ void zero_kernel(float* __restrict__ y) {
    int i = blockIdx.x * blockDim.x + threadIdx.x;
    if (i < NTOK * HDIM) y[i] = 0.f;
    if (i < NEXP) { g_cnt[i] = 0; g_pisum[i] = 0.f; }
}

__global__ void xconv_kernel(const float* __restrict__ x) {
    int i = blockIdx.x * blockDim.x + threadIdx.x;
    if (i < NTOK * HDIM) {
        float v = x[i];
        __nv_bfloat16 h = __float2bfloat16(v);
        __nv_bfloat16 l = __float2bfloat16(v - __bfloat162float(h));
        g_xhi[i] = h; g_xlo[i] = l;
    }
}

// fp32 -> bf16 hi/lo planes. Destination selected DEVICE-SIDE (which: 0=wg,1=wu,2=wd),
// dstOff is an element offset into the plane arrays (0 or shared-expert slot).
__global__ __launch_bounds__(256)
void wconv_kernel(const float4* __restrict__ src, int which, size_t dstOff, int n4) {
    int i = blockIdx.x * blockDim.x + threadIdx.x;
    if (i >= n4) return;
    __nv_bfloat16 *hb, *lb;
    if (which == 0)      { hb = g_wghi; lb = g_wglo; }
    else if (which == 1) { hb = g_wuhi; lb = g_wulo; }
    else                 { hb = g_wdhi; lb = g_wdlo; }
    uint2* hp = (uint2*)(hb + dstOff);
    uint2* lp = (uint2*)(lb + dstOff);
    float4 v = src[i];
    uint2 h, l;
    split2(v.x, v.y, h.x, l.x);
    split2(v.z, v.w, h.y, l.y);
    hp[i] = h; lp[i] = l;
}

// ---------------- gate ----------------
__global__ __launch_bounds__(256)
void gate_kernel(const float* __restrict__ x, const float* __restrict__ gw) {
    const int t = blockIdx.x;
    const float* xr = x + (size_t)t * HDIM;
    float acc[NEXP];
#pragma unroll
    for (int e = 0; e < NEXP; e++) acc[e] = 0.f;
    for (int h = threadIdx.x; h < HDIM; h += 256) {
        float xv = xr[h];
#pragma unroll
        for (int e = 0; e < NEXP; e++) acc[e] = fmaf(xv, gw[e * HDIM + h], acc[e]);
    }
#pragma unroll
    for (int e = 0; e < NEXP; e++)
        for (int o = 16; o > 0; o >>= 1) acc[e] += __shfl_down_sync(0xffffffffu, acc[e], o);

    __shared__ float red[8][NEXP];
    int warp = threadIdx.x >> 5, lane = threadIdx.x & 31;
    if (lane == 0) {
#pragma unroll
        for (int e = 0; e < NEXP; e++) red[warp][e] = acc[e];
    }
    __syncthreads();
    if (threadIdx.x == 0) {
        float lg[NEXP];
#pragma unroll
        for (int e = 0; e < NEXP; e++) {
            float s = 0.f;
            for (int w = 0; w < 8; w++) s += red[w][e];
            lg[e] = s;
        }
        float mx = lg[0];
#pragma unroll
        for (int e = 1; e < NEXP; e++) mx = fmaxf(mx, lg[e]);
        float p[NEXP]; float den = 0.f;
#pragma unroll
        for (int e = 0; e < NEXP; e++) { p[e] = __expf(lg[e] - mx); den += p[e]; }
#pragma unroll
        for (int e = 0; e < NEXP; e++) p[e] /= den;
#pragma unroll
        for (int e = 0; e < NEXP; e++) atomicAdd(&g_pisum[e], p[e]);
        int i1 = 0;
#pragma unroll
        for (int e = 1; e < NEXP; e++) if (p[e] > p[i1]) i1 = e;
        int i2 = -1;
#pragma unroll
        for (int e = 0; e < NEXP; e++) {
            if (e == i1) continue;
            if (i2 < 0 || p[e] > p[i2]) i2 = e;
        }
        float w1 = p[i1], w2 = p[i2];
        float s2 = w1 + w2 + 1e-20f;
        w1 /= s2; w2 /= s2;
        int pos1 = atomicAdd(&g_cnt[i1], 1);
        g_tok[i1 * NTOK + pos1] = t; g_wt[i1 * NTOK + pos1] = w1;
        int pos2 = atomicAdd(&g_cnt[i2], 1);
        g_tok[i2 * NTOK + pos2] = t; g_wt[i2 * NTOK + pos2] = w2;
    }
}

// =======================================================================
// gateup: act = silu(X Wg^T) * (X Wu^T)   tile 128x64, K chunk 32, 2-stage
// grid z: 0..7 routed experts, 8 = shared expert
// =======================================================================
#define STAGE  40960
#define GU_AHI 0
#define GU_ALO 10240
#define GU_BGH 20480
#define GU_BGL 25600
#define GU_BUH 30720
#define GU_BUL 35840
#define GU_TOK 81920
#define GU_SM  82432

__global__ __launch_bounds__(256, 2)
void gateup_mma() {
    extern __shared__ __align__(128) char sm[];
    const int z = blockIdx.z;
    const bool SH = (z == NEXP);
    const int nrows = SH ? NTOK : g_cnt[z];
    const int row0 = blockIdx.x * 128;
    if (row0 >= nrows) return;
    const int n0 = blockIdx.y * 64;

    const int tid = threadIdx.x, wid = tid >> 5, lane = tid & 31;
    int* toks = (int*)(sm + GU_TOK);
    if (tid < 128) {
        int r = row0 + tid;
        toks[tid] = (r < nrows) ? (SH ? r : g_tok[z * NTOK + r]) : 0;
    }
    __syncthreads();

    const uint32_t sb = smem_u32(sm);

    // A cp mapping: 2 thr/row, 32B per thread per plane
    const int arow = tid >> 1, aseg = tid & 1;
    const __nv_bfloat16* aph = g_xhi + (size_t)toks[arow] * HDIM + aseg * 16;
    const __nv_bfloat16* apl = g_xlo + (size_t)toks[arow] * HDIM + aseg * 16;
    const uint32_t aDH = sb + GU_AHI + arow * LDS_ROW + aseg * 32;
    const uint32_t aDL = sb + GU_ALO + arow * LDS_ROW + aseg * 32;

    // B cp mapping: 4 thr/row, 16B per thread per plane (4 planes)
    const int brow = tid >> 2, bseg = tid & 3;
    const size_t bOff = ((size_t)z * MDIM + n0 + brow) * HDIM + bseg * 8;
    const __nv_bfloat16* pgh = g_wghi + bOff;
    const __nv_bfloat16* pgl = g_wglo + bOff;
    const __nv_bfloat16* puh = g_wuhi + bOff;
    const __nv_bfloat16* pul = g_wulo + bOff;
    const uint32_t bD = brow * LDS_ROW + bseg * 16;
    const uint32_t bDgh = sb + GU_BGH + bD, bDgl = sb + GU_BGL + bD;
    const uint32_t bDuh = sb + GU_BUH + bD, bDul = sb + GU_BUL + bD;

#define GU_CP(c, stg) do { uint32_t o = (stg) * STAGE; size_t ko = (size_t)(c) * 32;  \
    cp16(aDH + o,      aph + ko);      cp16(aDH + o + 16, aph + ko + 8);              \
    cp16(aDL + o,      apl + ko);      cp16(aDL + o + 16, apl + ko + 8);              \
    cp16(bDgh + o, pgh + ko);  cp16(bDgl + o, pgl + ko);                              \
    cp16(bDuh + o, puh + ko);  cp16(bDul + o, pul + ko); } while (0)

    // compute fragment bases (warp grid 2m x 4n; warp tile 64x16)
    const int wm = wid & 1, wn = wid >> 1;
    const uint32_t aOffL = (lane & 15) * LDS_ROW + (lane >> 4) * 16;
    const uint32_t bOffL = (lane & 7) * LDS_ROW + ((lane >> 3) & 1) * 16;
    const uint32_t aHiB = sb + GU_AHI + (wm * 64) * LDS_ROW + aOffL;
    const uint32_t aLoB = sb + GU_ALO + (wm * 64) * LDS_ROW + aOffL;
    const uint32_t bGH = sb + GU_BGH + (wn * 16) * LDS_ROW + bOffL;
    const uint32_t bGL = sb + GU_BGL + (wn * 16) * LDS_ROW + bOffL;
    const uint32_t bUH = sb + GU_BUH + (wn * 16) * LDS_ROW + bOffL;
    const uint32_t bUL = sb + GU_BUL + (wn * 16) * LDS_ROW + bOffL;

    float accg[4][2][4] = {}, accu[4][2][4] = {};

    GU_CP(0, 0); CP_COMMIT();

    const int NC = HDIM / 32;
    for (int c = 0; c < NC; c++) {
        const uint32_t so = (c & 1) * STAGE;
        CP_WAIT0();
        __syncthreads();
        if (c + 1 < NC) { GU_CP(c + 1, (c + 1) & 1); CP_COMMIT(); }
#pragma unroll
        for (int ks = 0; ks < 2; ks++) {
            uint32_t ah[4][4], al[4][4];
#pragma unroll
            for (int i = 0; i < 4; i++) {
                LDSM4(ah[i], aHiB + so + i * (16 * LDS_ROW) + ks * 32);
                LDSM4(al[i], aLoB + so + i * (16 * LDS_ROW) + ks * 32);
            }
            uint32_t bgh[2][2], bgl[2][2], buh[2][2], bul[2][2];
#pragma unroll
            for (int j = 0; j < 2; j++) {
                LDSM2(bgh[j], bGH + so + j * (8 * LDS_ROW) + ks * 32);
                LDSM2(bgl[j], bGL + so + j * (8 * LDS_ROW) + ks * 32);
                LDSM2(buh[j], bUH + so + j * (8 * LDS_ROW) + ks * 32);
                LDSM2(bul[j], bUL + so + j * (8 * LDS_ROW) + ks * 32);
            }
#pragma unroll
            for (int i = 0; i < 4; i++)
#pragma unroll
                for (int j = 0; j < 2; j++) {
                    MMA(accg[i][j], ah[i], bgh[j]);
                    MMA(accg[i][j], ah[i], bgl[j]);
                    MMA(accg[i][j], al[i], bgh[j]);
                    MMA(accu[i][j], ah[i], buh[j]);
                    MMA(accu[i][j], ah[i], bul[j]);
                    MMA(accu[i][j], al[i], buh[j]);
                }
        }
    }

    // epilogue: silu(g)*u -> bf16 planes
    const int mrow = wm * 64 + (lane >> 2);
    const int col0 = n0 + wn * 16 + (lane & 3) * 2;
#pragma unroll
    for (int i = 0; i < 4; i++)
#pragma unroll
        for (int j = 0; j < 2; j++) {
            int col = col0 + j * 8;
#pragma unroll
            for (int half = 0; half < 2; half++) {
                int r = row0 + mrow + i * 16 + half * 8;
                if (r < nrows) {
                    float gv0 = accg[i][j][half * 2],     uv0 = accu[i][j][half * 2];
                    float gv1 = accg[i][j][half * 2 + 1], uv1 = accu[i][j][half * 2 + 1];
                    float a0 = (gv0 / (1.f + __expf(-gv0))) * uv0;
                    float a1 = (gv1 / (1.f + __expf(-gv1))) * uv1;
                    uint32_t hi, lo;
                    split2(a0, a1, hi, lo);
                    size_t idx = ((size_t)z * NTOK + r) * MDIM + col;
                    *(uint32_t*)(g_ahi + idx) = hi;
                    *(uint32_t*)(g_alo + idx) = lo;
                }
            }
        }
#undef GU_CP
}

// =======================================================================
// down: y[tok] += w * (act @ Wd^T)   tile 128x128, K chunk 32, 2-stage
// =======================================================================
#define DN_AHI 0
#define DN_ALO 10240
#define DN_BH  20480
#define DN_BL  30720
#define DN_TOK 81920
#define DN_WTS 82432
#define DN_SM  82944

__global__ __launch_bounds__(256, 2)
void down_mma(float* __restrict__ y) {
    extern __shared__ __align__(128) char sm[];
    const int z = blockIdx.z;
    const bool SH = (z == NEXP);
    const int nrows = SH ? NTOK : g_cnt[z];
    const int row0 = blockIdx.x * 128;
    if (row0 >= nrows) return;
    const int h0 = blockIdx.y * 128;

    const int tid = threadIdx.x, wid = tid >> 5, lane = tid & 31;
    int* toks = (int*)(sm + DN_TOK);
    float* wts = (float*)(sm + DN_WTS);
    if (tid < 128) {
        int r = row0 + tid;
        if (r < nrows) {
            toks[tid] = SH ? r : g_tok[z * NTOK + r];
            wts[tid]  = SH ? 1.f : g_wt[z * NTOK + r];
        } else { toks[tid] = 0; wts[tid] = 0.f; }
    }
    __syncthreads();

    const uint32_t sb = smem_u32(sm);

    // A + B cp mapping: 2 thr/row, 32B per thread per plane
    const int arow = tid >> 1, aseg = tid & 1;
    const __nv_bfloat16* aph = g_ahi + ((size_t)z * NTOK + row0 + arow) * MDIM + aseg * 16;
    const __nv_bfloat16* apl = g_alo + ((size_t)z * NTOK + row0 + arow) * MDIM + aseg * 16;
    const size_t bOff = ((size_t)z * HDIM + h0 + arow) * MDIM + aseg * 16;
    const __nv_bfloat16* pbh = g_wdhi + bOff;
    const __nv_bfloat16* pbl = g_wdlo + bOff;
    const uint32_t aDH = sb + DN_AHI + arow * LDS_ROW + aseg * 32;
    const uint32_t aDL = sb + DN_ALO + arow * LDS_ROW + aseg * 32;
    const uint32_t bDH = sb + DN_BH + arow * LDS_ROW + aseg * 32;
    const uint32_t bDL = sb + DN_BL + arow * LDS_ROW + aseg * 32;

#define DN_CP(c, stg) do { uint32_t o = (stg) * STAGE; size_t ko = (size_t)(c) * 32;  \
    cp16(aDH + o,      aph + ko);      cp16(aDH + o + 16, aph + ko + 8);              \
    cp16(aDL + o,      apl + ko);      cp16(aDL + o + 16, apl + ko + 8);              \
    cp16(bDH + o,      pbh + ko);      cp16(bDH + o + 16, pbh + ko + 8);              \
    cp16(bDL + o,      pbl + ko);      cp16(bDL + o + 16, pbl + ko + 8); } while (0)

    const int wm = wid & 1, wn = wid >> 1;   // warp tile 64x32
    const uint32_t aOffL = (lane & 15) * LDS_ROW + (lane >> 4) * 16;
    const uint32_t bOffL = (lane & 7) * LDS_ROW + ((lane >> 3) & 1) * 16;
    const uint32_t aHiB = sb + DN_AHI + (wm * 64) * LDS_ROW + aOffL;
    const uint32_t aLoB = sb + DN_ALO + (wm * 64) * LDS_ROW + aOffL;
    const uint32_t bHB = sb + DN_BH + (wn * 32) * LDS_ROW + bOffL;
    const uint32_t bLB = sb + DN_BL + (wn * 32) * LDS_ROW + bOffL;

    float acc[4][4][4] = {};

    DN_CP(0, 0); CP_COMMIT();

    const int NC = MDIM / 32;
    for (int c = 0; c < NC; c++) {
        const uint32_t so = (c & 1) * STAGE;
        CP_WAIT0();
        __syncthreads();
        if (c + 1 < NC) { DN_CP(c + 1, (c + 1) & 1); CP_COMMIT(); }
#pragma unroll
        for (int ks = 0; ks < 2; ks++) {
            uint32_t ah[4][4], al[4][4];
#pragma unroll
            for (int i = 0; i < 4; i++) {
                LDSM4(ah[i], aHiB + so + i * (16 * LDS_ROW) + ks * 32);
                LDSM4(al[i], aLoB + so + i * (16 * LDS_ROW) + ks * 32);
            }
            uint32_t bh[4][2], bl[4][2];
#pragma unroll
            for (int j = 0; j < 4; j++) {
                LDSM2(bh[j], bHB + so + j * (8 * LDS_ROW) + ks * 32);
                LDSM2(bl[j], bLB + so + j * (8 * LDS_ROW) + ks * 32);
            }
#pragma unroll
            for (int i = 0; i < 4; i++)
#pragma unroll
                for (int j = 0; j < 4; j++) {
                    MMA(acc[i][j], ah[i], bh[j]);
                    MMA(acc[i][j], ah[i], bl[j]);
                    MMA(acc[i][j], al[i], bh[j]);
                }
        }
    }

    // epilogue: weighted atomic scatter
    const int mrow = wm * 64 + (lane >> 2);
    const int col0 = h0 + wn * 32 + (lane & 3) * 2;
#pragma unroll
    for (int i = 0; i < 4; i++)
#pragma unroll
        for (int half = 0; half < 2; half++) {
            int rl = mrow + i * 16 + half * 8;
            int r = row0 + rl;
            if (r < nrows) {
                float w = wts[rl];
                int tok = toks[rl];
                float* yp = y + (size_t)tok * HDIM;
#pragma unroll
                for (int j = 0; j < 4; j++) {
                    int col = col0 + j * 8;
                    atomicAdd(&yp[col],     acc[i][j][half * 2]     * w);
                    atomicAdd(&yp[col + 1], acc[i][j][half * 2 + 1] * w);
                }
            }
        }
#undef DN_CP
}

// ---------------- aux loss ----------------
__global__ void aux_kernel(float* __restrict__ p) {
    float a = 0.f;
#pragma unroll
    for (int e = 0; e < NEXP; e++) {
        float ce = (float)g_cnt[e] * ((float)NEXP / (float)(NTOK * 2));
        float pi = g_pisum[e] / (float)NTOK;
        a += ce * pi;
    }
    *p = a * 0.001f;
}

// ---------------- launch ----------------
extern "C" void kernel_launch(void* const* d_in, const int* in_sizes, int n_in,
                              void* d_out, int out_size) {
    (void)in_sizes; (void)n_in;
    const float* x   = (const float*)d_in[0];
    const float* gw  = (const float*)d_in[1];
    const float* wgt = (const float*)d_in[2];
    const float* wup = (const float*)d_in[3];
    const float* wdn = (const float*)d_in[4];
    const float* shg = (const float*)d_in[5];
    const float* shu = (const float*)d_in[6];
    const float* shd = (const float*)d_in[7];
    float* y = (float*)d_out;

    cudaFuncSetAttribute(gateup_mma, cudaFuncAttributeMaxDynamicSharedMemorySize, GU_SM);
    cudaFuncSetAttribute(down_mma,   cudaFuncAttributeMaxDynamicSharedMemorySize, DN_SM);

    zero_kernel<<<(NTOK * HDIM + 255) / 256, 256>>>(y);
    gate_kernel<<<NTOK, 256>>>(x, gw);
    xconv_kernel<<<(NTOK * HDIM + 255) / 256, 256>>>(x);

    // weight plane conversion (device-side destination selection; slot 8 = shared)
    const int NE4 = NEXP * MDIM * HDIM / 4;   // routed experts, x4 vectorized
    const int NS4 = MDIM * HDIM / 4;          // shared expert
    const size_t SOFF = (size_t)NEXP * MDIM * HDIM;
    wconv_kernel<<<(NE4 + 255) / 256, 256>>>((const float4*)wgt, 0, 0, NE4);
    wconv_kernel<<<(NE4 + 255) / 256, 256>>>((const float4*)wup, 1, 0, NE4);
    wconv_kernel<<<(NE4 + 255) / 256, 256>>>((const float4*)wdn, 2, 0, NE4);
    wconv_kernel<<<(NS4 + 255) / 256, 256>>>((const float4*)shg, 0, SOFF, NS4);
    wconv_kernel<<<(NS4 + 255) / 256, 256>>>((const float4*)shu, 1, SOFF, NS4);
    wconv_kernel<<<(NS4 + 255) / 256, 256>>>((const float4*)shd, 2, SOFF, NS4);

    gateup_mma<<<dim3(NTOK / 128, MDIM / 64, NEXP + 1), 256, GU_SM>>>();
    down_mma<<<dim3(NTOK / 128, HDIM / 128, NEXP + 1), 256, DN_SM>>>(y);

    if (out_size > NTOK * HDIM)
        aux_kernel<<<1, 1>>>(y + NTOK * HDIM);
}